// round 16
// baseline (speedup 1.0000x reference)
#include <cuda_runtime.h>
#include <cuda_fp16.h>
#include <cstdint>

#define B_   2
#define T_   2048
#define C_   2048
#define NH   16
#define HD   128
#define ROWS (B_ * T_)          // 4096
#define QKVN (3 * C_)           // 6144

// Scratch (device globals: allocation-free rule)
__device__ __half g_qkv[(size_t)ROWS * QKVN];   // 50.3 MB
__device__ __half g_y[(size_t)ROWS * C_];       // 16.8 MB
__device__ __half g_xh[(size_t)ROWS * C_];      // x fp16
__device__ __half g_wat[(size_t)QKVN * C_];     // W_attn^T fp16 [N][K]
__device__ __half g_wpt[(size_t)C_ * C_];       // W_proj^T fp16 [N][K]

// ---------------------------------------------------------------------------
// PTX helpers
// ---------------------------------------------------------------------------
__device__ __forceinline__ void mma_f16(float* d, const uint32_t* a,
                                        const uint32_t* b) {
    asm volatile(
        "mma.sync.aligned.m16n8k16.row.col.f32.f16.f16.f32 "
        "{%0,%1,%2,%3},{%4,%5,%6,%7},{%8,%9},{%0,%1,%2,%3};\n"
        : "+f"(d[0]), "+f"(d[1]), "+f"(d[2]), "+f"(d[3])
        : "r"(a[0]), "r"(a[1]), "r"(a[2]), "r"(a[3]), "r"(b[0]), "r"(b[1]));
}

#define CP_ASYNC16(dst, src) \
    asm volatile("cp.async.cg.shared.global [%0], [%1], 16;\n" :: "r"(dst), "l"(src))
#define CP_COMMIT() asm volatile("cp.async.commit_group;\n")
#define CP_WAIT1()  asm volatile("cp.async.wait_group 1;\n")

__device__ __forceinline__ uint32_t pack_h2(float lo, float hi) {
    __half2 h = __floats2half2_rn(lo, hi);
    return *(uint32_t*)&h;
}

// ---------------------------------------------------------------------------
// fp32 -> fp16 elementwise
// ---------------------------------------------------------------------------
__global__ __launch_bounds__(256) void f2h_kernel(
    const float4* __restrict__ in, __half2* __restrict__ out, int n4)
{
    int i = blockIdx.x * blockDim.x + threadIdx.x;
    if (i < n4) {
        float4 v = in[i];
        out[2 * i + 0] = __floats2half2_rn(v.x, v.y);
        out[2 * i + 1] = __floats2half2_rn(v.z, v.w);
    }
}

// ---------------------------------------------------------------------------
// Transpose + convert: WT[n][k] = fp16(W[k][n])
// ---------------------------------------------------------------------------
__global__ __launch_bounds__(256) void transpose_h_kernel(
    const float* __restrict__ W, __half* __restrict__ WT, int K, int N)
{
    __shared__ float t[32][33];
    const int tx = threadIdx.x, ty = threadIdx.y;
    const int n = blockIdx.x * 32 + tx;
    const int k0 = blockIdx.y * 32;
#pragma unroll
    for (int i = 0; i < 4; i++)
        t[ty + i * 8][tx] = W[(size_t)(k0 + ty + i * 8) * N + n];
    __syncthreads();
    const int k = k0 + tx;
    const int n0 = blockIdx.x * 32;
#pragma unroll
    for (int i = 0; i < 4; i++)
        WT[(size_t)(n0 + ty + i * 8) * K + k] =
            __float2half_rn(t[tx][ty + i * 8]);
}

// ---------------------------------------------------------------------------
// fp16 GEMM + bias: C[M,N] = A[M,K] @ BT[N,K]^T + bias[N]
// 256x128 CTA tile, 512 threads (16 warps, each 64x32), K-chunk 32,
// 2-stage cp.async, compute-then-prefetch order (R11-proven).
// ---------------------------------------------------------------------------
#define GROW 80                          // bytes per smem row (32 halves + pad)
#define STG_A (256 * GROW)               // 20480
#define STG_B (128 * GROW)               // 10240
#define STG_BYTES (STG_A + STG_B)        // 30720
#define GEMM_SMEM (2 * STG_BYTES)        // 61440

template <bool OUTHALF>
__global__ __launch_bounds__(512, 1) void gemm_f16_kernel(
    const __half* __restrict__ A, const __half* __restrict__ BT,
    const float* __restrict__ bias, void* __restrict__ Cv,
    int K, int NOUT)
{
    extern __shared__ uint8_t smb[];
    const uint32_t sb = (uint32_t)__cvta_generic_to_shared(smb);

    const int tid = threadIdx.x;
    const int lane = tid & 31, warp = tid >> 5;
    const int gr = lane >> 2, gc = lane & 3;
    const int wm = (warp >> 2) * 64, wn = (warp & 3) * 32;
    const int bx = blockIdx.x, by = blockIdx.y;
    const int NK = K / 32;

    // cp.async mapping (512 threads):
    //  A: row = tid>>1 (0..255), units {au, au+1} where au = (tid&1)*2
    //  B: row = tid>>2 (0..127), unit  = tid&3
    const int ar = tid >> 1, au = (tid & 1) * 2;
    const int rb = tid >> 2, ub = tid & 3;
    const __half* Ag = A + (size_t)(by * 256 + ar) * K + au * 8;
    const __half* Bg = BT + (size_t)(bx * 128 + rb) * K + ub * 8;

    float acc[4][4][4];
#pragma unroll
    for (int t = 0; t < 4; t++)
#pragma unroll
        for (int j = 0; j < 4; j++)
#pragma unroll
            for (int q = 0; q < 4; q++) acc[t][j][q] = 0.0f;

    // prologue: chunks 0,1
#pragma unroll
    for (int p = 0; p < 2; p++) {
        const uint32_t st = sb + p * STG_BYTES;
#pragma unroll
        for (int u = 0; u < 2; u++)
            CP_ASYNC16(st + ar * GROW + (au + u) * 16,
                       Ag + (size_t)p * 32 + u * 8);
        CP_ASYNC16(st + STG_A + rb * GROW + ub * 16,
                   Bg + (size_t)p * 32);
        CP_COMMIT();
    }

    int stage = 0;
    for (int c = 0; c < NK; c++) {
        CP_WAIT1();
        __syncthreads();

        const uint32_t Asb = sb + stage * STG_BYTES;
        const uint32_t Bsb = Asb + STG_A;

#pragma unroll
        for (int s = 0; s < 2; s++) {           // two k16 steps
            uint32_t af[4][4], bf[4][2];
#pragma unroll
            for (int t = 0; t < 4; t++) {
                const uint32_t ap = Asb + (wm + t * 16 + gr) * GROW + s * 32 + gc * 4;
                af[t][0] = *(const uint32_t*)(smb + (ap - sb));
                af[t][1] = *(const uint32_t*)(smb + (ap - sb) + 8 * GROW);
                af[t][2] = *(const uint32_t*)(smb + (ap - sb) + 16);
                af[t][3] = *(const uint32_t*)(smb + (ap - sb) + 8 * GROW + 16);
            }
#pragma unroll
            for (int j = 0; j < 4; j++) {
                const uint32_t bp = Bsb + (wn + j * 8 + gr) * GROW + s * 32 + gc * 4;
                bf[j][0] = *(const uint32_t*)(smb + (bp - sb));
                bf[j][1] = *(const uint32_t*)(smb + (bp - sb) + 16);
            }
#pragma unroll
            for (int t = 0; t < 4; t++)
#pragma unroll
                for (int j = 0; j < 4; j++)
                    mma_f16(acc[t][j], af[t], bf[j]);
        }

        __syncthreads();

        const int kn = c + 2;
        if (kn < NK) {
            const uint32_t st = sb + stage * STG_BYTES;
#pragma unroll
            for (int u = 0; u < 2; u++)
                CP_ASYNC16(st + ar * GROW + (au + u) * 16,
                           Ag + (size_t)kn * 32 + u * 8);
            CP_ASYNC16(st + STG_A + rb * GROW + ub * 16,
                       Bg + (size_t)kn * 32);
        }
        CP_COMMIT();
        stage ^= 1;
    }

    // epilogue
    const int col0 = bx * 128 + wn + 2 * gc;
    const int row0 = by * 256 + wm + gr;
    float2 bv[4];
#pragma unroll
    for (int j = 0; j < 4; j++)
        bv[j] = *(const float2*)(bias + col0 + j * 8);

#pragma unroll
    for (int t = 0; t < 4; t++) {
        const int r = row0 + t * 16;
#pragma unroll
        for (int j = 0; j < 4; j++) {
            float v0x = acc[t][j][0] + bv[j].x;
            float v0y = acc[t][j][1] + bv[j].y;
            float v1x = acc[t][j][2] + bv[j].x;
            float v1y = acc[t][j][3] + bv[j].y;
            if (OUTHALF) {
                __half* Cm = (__half*)Cv;
                *(__half2*)(Cm + (size_t)r * NOUT + col0 + j * 8) =
                    __floats2half2_rn(v0x, v0y);
                *(__half2*)(Cm + (size_t)(r + 8) * NOUT + col0 + j * 8) =
                    __floats2half2_rn(v1x, v1y);
            } else {
                float* Cm = (float*)Cv;
                float2 w0 = {v0x, v0y}, w1 = {v1x, v1y};
                *(float2*)(Cm + (size_t)r * NOUT + col0 + j * 8) = w0;
                *(float2*)(Cm + (size_t)(r + 8) * NOUT + col0 + j * 8) = w1;
            }
        }
    }
}

// ---------------------------------------------------------------------------
// fp16 tensor-core flash attention (causal) — R11-proven version, unchanged.
// BQ=128, BK=64, HD=128, 256 threads (8 warps x 16 query rows).
// smem bytes: sQ[128][272] | sK[64][272] | sVt[128][144] | sP[128][144]
// ---------------------------------------------------------------------------
#define SQB 272
#define SKB 272
#define SVB 144
#define SPB 144
#define SQ_OFF  0
#define SK_OFF  (128 * SQB)                  // 34816
#define SVT_OFF (SK_OFF + 64 * SKB)          // 52224
#define SP_OFF  (SVT_OFF + 128 * SVB)        // 70656
#define FLASH_SMEM (SP_OFF + 128 * SPB)      // 89088

__global__ __launch_bounds__(256, 1) void flash_f16_kernel(
    const __half* __restrict__ qkv, __half* __restrict__ y)
{
    extern __shared__ uint8_t smb[];

    const int qt = blockIdx.x, h = blockIdx.y, b = blockIdx.z;
    const int tid = threadIdx.x;
    const int lane = tid & 31, warp = tid >> 5;
    const int gr = lane >> 2, gc = lane & 3;
    const int m0 = warp * 16;
    const float scale = 0.08838834764831845f; // 1/sqrt(128)

    // ---- load Q tile ----
    {
        const int row = tid & 127;
        const int d0 = (tid >> 7) * 64;       // halves
        const uint4* qp = (const uint4*)(qkv
            + ((size_t)(b * T_ + qt * 128 + row)) * QKVN + h * HD + d0);
        uint8_t* dst = smb + SQ_OFF + row * SQB + d0 * 2;
#pragma unroll
        for (int it = 0; it < 8; it++)
            *(uint4*)(dst + it * 16) = qp[it];
    }

    float o[16][4];
#pragma unroll
    for (int j = 0; j < 16; j++)
#pragma unroll
        for (int c = 0; c < 4; c++) o[j][c] = 0.0f;
    float mrow[2] = {-1e30f, -1e30f};
    float lrow[2] = {0.0f, 0.0f};

    const int ktmax = 2 * qt + 1;
    for (int kt = 0; kt <= ktmax; kt++) {
        __syncthreads();

        // ---- load K (row-major) + V (transposed) ----
        {
            const int row = tid & 63;
            const int d0 = (tid >> 6) * 32;   // halves
            const __half* kp = qkv + ((size_t)(b * T_ + kt * 64 + row)) * QKVN
                               + C_ + h * HD + d0;
            const uint4* kpu = (const uint4*)kp;
            const uint4* vpu = (const uint4*)(kp + C_);
            uint8_t* kdst = smb + SK_OFF + row * SKB + d0 * 2;
#pragma unroll
            for (int it = 0; it < 4; it++)
                *(uint4*)(kdst + it * 16) = kpu[it];
#pragma unroll
            for (int it = 0; it < 4; it++) {
                uint4 v = vpu[it];
                uint32_t w[4] = {v.x, v.y, v.z, v.w};
                const int dbase = d0 + it * 8;
#pragma unroll
                for (int q = 0; q < 4; q++) {
                    uint8_t* p0 = smb + SVT_OFF + (dbase + 2 * q) * SVB + row * 2;
                    uint8_t* p1 = p0 + SVB;
                    *(uint16_t*)p0 = (uint16_t)(w[q] & 0xFFFFu);
                    *(uint16_t*)p1 = (uint16_t)(w[q] >> 16);
                }
            }
        }
        __syncthreads();

        if (qt * 128 + m0 + 15 < kt * 64) continue;

        // ---- S = Q @ K^T  (8 k16 steps, n64) ----
        float s[8][4];
#pragma unroll
        for (int j = 0; j < 8; j++)
#pragma unroll
            for (int c = 0; c < 4; c++) s[j][c] = 0.0f;

#pragma unroll
        for (int ks = 0; ks < 8; ks++) {
            uint32_t a[4];
            const uint8_t* ap = smb + SQ_OFF + (m0 + gr) * SQB + ks * 32 + gc * 4;
            a[0] = *(const uint32_t*)(ap);
            a[1] = *(const uint32_t*)(ap + 8 * SQB);
            a[2] = *(const uint32_t*)(ap + 16);
            a[3] = *(const uint32_t*)(ap + 8 * SQB + 16);
#pragma unroll
            for (int j = 0; j < 8; j++) {
                uint32_t bfr[2];
                const uint8_t* bp = smb + SK_OFF + (j * 8 + gr) * SKB + ks * 32 + gc * 4;
                bfr[0] = *(const uint32_t*)(bp);
                bfr[1] = *(const uint32_t*)(bp + 16);
                mma_f16(s[j], a, bfr);
            }
        }

        // ---- online softmax ----
#pragma unroll
        for (int r = 0; r < 2; r++) {
            const int qg = qt * 128 + m0 + gr + 8 * r;
            const bool need_mask = (kt * 64 + 63 > qg);
            float rm = -1e30f;
#pragma unroll
            for (int j = 0; j < 8; j++) {
#pragma unroll
                for (int c = 0; c < 2; c++) {
                    float v = s[j][2 * r + c] * scale;
                    if (need_mask && (kt * 64 + j * 8 + 2 * gc + c) > qg)
                        v = -1e30f;
                    s[j][2 * r + c] = v;
                    rm = fmaxf(rm, v);
                }
            }
            rm = fmaxf(rm, __shfl_xor_sync(0xffffffffu, rm, 1));
            rm = fmaxf(rm, __shfl_xor_sync(0xffffffffu, rm, 2));
            const float mnew = fmaxf(mrow[r], rm);
            const float corr = __expf(mrow[r] - mnew);
            float rsum = 0.0f;
#pragma unroll
            for (int j = 0; j < 8; j++) {
#pragma unroll
                for (int c = 0; c < 2; c++) {
                    float p = __expf(s[j][2 * r + c] - mnew);
                    s[j][2 * r + c] = p;
                    rsum += p;
                }
            }
            rsum += __shfl_xor_sync(0xffffffffu, rsum, 1);
            rsum += __shfl_xor_sync(0xffffffffu, rsum, 2);
            lrow[r] = lrow[r] * corr + rsum;
            mrow[r] = mnew;
#pragma unroll
            for (int j = 0; j < 16; j++) {
                o[j][2 * r + 0] *= corr;
                o[j][2 * r + 1] *= corr;
            }
        }

        // ---- stage P (fp16) ----
#pragma unroll
        for (int j = 0; j < 8; j++) {
            uint8_t* p0 = smb + SP_OFF + (m0 + gr) * SPB + j * 16 + gc * 4;
            *(uint32_t*)p0 = pack_h2(s[j][0], s[j][1]);
            *(uint32_t*)(p0 + 8 * SPB) = pack_h2(s[j][2], s[j][3]);
        }
        __syncwarp();

        // ---- O += P @ V  (4 k16 steps, n128) ----
#pragma unroll
        for (int ks = 0; ks < 4; ks++) {
            uint32_t a[4];
            const uint8_t* ap = smb + SP_OFF + (m0 + gr) * SPB + ks * 32 + gc * 4;
            a[0] = *(const uint32_t*)(ap);
            a[1] = *(const uint32_t*)(ap + 8 * SPB);
            a[2] = *(const uint32_t*)(ap + 16);
            a[3] = *(const uint32_t*)(ap + 8 * SPB + 16);
#pragma unroll
            for (int j = 0; j < 16; j++) {
                uint32_t bfr[2];
                const uint8_t* bp = smb + SVT_OFF + (j * 8 + gr) * SVB + ks * 32 + gc * 4;
                bfr[0] = *(const uint32_t*)(bp);
                bfr[1] = *(const uint32_t*)(bp + 16);
                mma_f16(o[j], a, bfr);
            }
        }
    }

    // ---- epilogue: O/l -> y (fp16) ----
    const float inv0 = 1.0f / lrow[0];
    const float inv1 = 1.0f / lrow[1];
#pragma unroll
    for (int r = 0; r < 2; r++) {
        const float inv = r ? inv1 : inv0;
        __half* yr = y + ((size_t)(b * T_ + qt * 128 + m0 + gr + 8 * r)) * C_
                     + h * HD + 2 * gc;
#pragma unroll
        for (int j = 0; j < 16; j++)
            *(__half2*)(yr + j * 8) =
                __floats2half2_rn(o[j][2 * r + 0] * inv, o[j][2 * r + 1] * inv);
    }
}

// ---------------------------------------------------------------------------
extern "C" void kernel_launch(void* const* d_in, const int* in_sizes, int n_in,
                              void* d_out, int out_size)
{
    const float* x      = (const float*)d_in[0];
    const float* W_attn = (const float*)d_in[1];
    const float* b_attn = (const float*)d_in[2];
    const float* W_proj = (const float*)d_in[3];
    const float* b_proj = (const float*)d_in[4];
    float* out = (float*)d_out;

    __half *qkv, *y, *xh, *wat, *wpt;
    cudaGetSymbolAddress((void**)&qkv, g_qkv);
    cudaGetSymbolAddress((void**)&y, g_y);
    cudaGetSymbolAddress((void**)&xh, g_xh);
    cudaGetSymbolAddress((void**)&wat, g_wat);
    cudaGetSymbolAddress((void**)&wpt, g_wpt);

    cudaFuncSetAttribute(gemm_f16_kernel<true>,
                         cudaFuncAttributeMaxDynamicSharedMemorySize, GEMM_SMEM);
    cudaFuncSetAttribute(gemm_f16_kernel<false>,
                         cudaFuncAttributeMaxDynamicSharedMemorySize, GEMM_SMEM);
    cudaFuncSetAttribute(flash_f16_kernel,
                         cudaFuncAttributeMaxDynamicSharedMemorySize, FLASH_SMEM);

    // 0) convert operands to fp16
    {
        int n4x = (ROWS * C_) / 4;
        f2h_kernel<<<(n4x + 255) / 256, 256>>>(
            (const float4*)x, (__half2*)xh, n4x);
        transpose_h_kernel<<<dim3(QKVN / 32, C_ / 32), dim3(32, 8)>>>(
            W_attn, wat, C_, QKVN);
        transpose_h_kernel<<<dim3(C_ / 32, C_ / 32), dim3(32, 8)>>>(
            W_proj, wpt, C_, C_);
    }

    // 1) QKV projection (fp16 out)
    gemm_f16_kernel<true><<<dim3(QKVN / 128, ROWS / 256), 512, GEMM_SMEM>>>(
        xh, wat, b_attn, qkv, C_, QKVN);
    // 2) Causal flash attention
    flash_f16_kernel<<<dim3(T_ / 128, NH, B_), 256, FLASH_SMEM>>>(qkv, y);
    // 3) Output projection (fp32 out)
    gemm_f16_kernel<false><<<dim3(C_ / 128, ROWS / 256), 512, GEMM_SMEM>>>(
        y, wpt, b_proj, out, C_, C_);
}

// round 17
// speedup vs baseline: 1.0619x; 1.0619x over previous
#include <cuda_runtime.h>
#include <cuda_fp16.h>
#include <cstdint>

#define B_   2
#define T_   2048
#define C_   2048
#define NH   16
#define HD   128
#define ROWS (B_ * T_)          // 4096
#define QKVN (3 * C_)           // 6144

// Scratch (device globals: allocation-free rule)
__device__ __half g_qkv[(size_t)ROWS * QKVN];   // 50.3 MB
__device__ __half g_y[(size_t)ROWS * C_];       // 16.8 MB
__device__ __half g_xh[(size_t)ROWS * C_];      // x fp16
__device__ __half g_wat[(size_t)QKVN * C_];     // W_attn^T fp16 [N][K]
__device__ __half g_wpt[(size_t)C_ * C_];       // W_proj^T fp16 [N][K]

// ---------------------------------------------------------------------------
// PTX helpers
// ---------------------------------------------------------------------------
__device__ __forceinline__ void mma_f16(float* d, const uint32_t* a,
                                        const uint32_t* b) {
    asm volatile(
        "mma.sync.aligned.m16n8k16.row.col.f32.f16.f16.f32 "
        "{%0,%1,%2,%3},{%4,%5,%6,%7},{%8,%9},{%0,%1,%2,%3};\n"
        : "+f"(d[0]), "+f"(d[1]), "+f"(d[2]), "+f"(d[3])
        : "r"(a[0]), "r"(a[1]), "r"(a[2]), "r"(a[3]), "r"(b[0]), "r"(b[1]));
}

#define CP_ASYNC16(dst, src) \
    asm volatile("cp.async.cg.shared.global [%0], [%1], 16;\n" :: "r"(dst), "l"(src))
#define CP_COMMIT() asm volatile("cp.async.commit_group;\n")
#define CP_WAIT1()  asm volatile("cp.async.wait_group 1;\n")

__device__ __forceinline__ uint32_t pack_h2(float lo, float hi) {
    __half2 h = __floats2half2_rn(lo, hi);
    return *(uint32_t*)&h;
}

// ---------------------------------------------------------------------------
// fp32 -> fp16 elementwise
// ---------------------------------------------------------------------------
__global__ __launch_bounds__(256) void f2h_kernel(
    const float4* __restrict__ in, __half2* __restrict__ out, int n4)
{
    int i = blockIdx.x * blockDim.x + threadIdx.x;
    if (i < n4) {
        float4 v = in[i];
        out[2 * i + 0] = __floats2half2_rn(v.x, v.y);
        out[2 * i + 1] = __floats2half2_rn(v.z, v.w);
    }
}

// ---------------------------------------------------------------------------
// Transpose + convert: WT[n][k] = fp16(W[k][n])
// ---------------------------------------------------------------------------
__global__ __launch_bounds__(256) void transpose_h_kernel(
    const float* __restrict__ W, __half* __restrict__ WT, int K, int N)
{
    __shared__ float t[32][33];
    const int tx = threadIdx.x, ty = threadIdx.y;
    const int n = blockIdx.x * 32 + tx;
    const int k0 = blockIdx.y * 32;
#pragma unroll
    for (int i = 0; i < 4; i++)
        t[ty + i * 8][tx] = W[(size_t)(k0 + ty + i * 8) * N + n];
    __syncthreads();
    const int k = k0 + tx;
    const int n0 = blockIdx.x * 32;
#pragma unroll
    for (int i = 0; i < 4; i++)
        WT[(size_t)(n0 + ty + i * 8) * K + k] =
            __float2half_rn(t[tx][ty + i * 8]);
}

// ---------------------------------------------------------------------------
// fp16 GEMM + bias: C[M,N] = A[M,K] @ BT[N,K]^T + bias[N]
// 256x128 tile, 256 threads (8 warps, each 64x64), K-chunk 32,
// 2-stage cp.async. (R15 config — best measured: 406 us on QKV.)
// ---------------------------------------------------------------------------
#define GROW 80                          // bytes per smem row (32 halves + pad)
#define STG_A (256 * GROW)               // 20480
#define STG_B (128 * GROW)               // 10240
#define STG_BYTES (STG_A + STG_B)        // 30720
#define GEMM_SMEM (2 * STG_BYTES)        // 61440

template <bool OUTHALF>
__global__ __launch_bounds__(256, 1) void gemm_f16_kernel(
    const __half* __restrict__ A, const __half* __restrict__ BT,
    const float* __restrict__ bias, void* __restrict__ Cv,
    int K, int NOUT)
{
    extern __shared__ uint8_t smb[];
    const uint32_t sb = (uint32_t)__cvta_generic_to_shared(smb);

    const int tid = threadIdx.x;
    const int lane = tid & 31, warp = tid >> 5;
    const int gr = lane >> 2, gc = lane & 3;
    const int wm = (warp >> 1) * 64, wn = (warp & 1) * 64;
    const int bx = blockIdx.x, by = blockIdx.y;
    const int NK = K / 32;

    // cp.async mapping
    const int ar = tid >> 1, au = (tid & 1) * 2;
    const __half* Ag = A + (size_t)(by * 256 + ar) * K + au * 8;
    const __half* Bg = BT + (size_t)(bx * 128 + ar) * K + au * 8;

    float acc[4][8][4];
#pragma unroll
    for (int t = 0; t < 4; t++)
#pragma unroll
        for (int j = 0; j < 8; j++)
#pragma unroll
            for (int q = 0; q < 4; q++) acc[t][j][q] = 0.0f;

    // prologue: chunks 0,1
#pragma unroll
    for (int p = 0; p < 2; p++) {
        const uint32_t st = sb + p * STG_BYTES;
#pragma unroll
        for (int u = 0; u < 2; u++) {
            CP_ASYNC16(st + ar * GROW + (au + u) * 16,
                       Ag + (size_t)p * 32 + u * 8);
            CP_ASYNC16(st + (ar + 128) * GROW + (au + u) * 16,
                       Ag + (size_t)128 * K + p * 32 + u * 8);
            CP_ASYNC16(st + STG_A + ar * GROW + (au + u) * 16,
                       Bg + (size_t)p * 32 + u * 8);
        }
        CP_COMMIT();
    }

    int stage = 0;
    for (int c = 0; c < NK; c++) {
        CP_WAIT1();
        __syncthreads();

        const uint32_t Asb = sb + stage * STG_BYTES;
        const uint32_t Bsb = Asb + STG_A;

        // hoisted fragment loads (both k16 steps)
        uint32_t af[2][4][4], bf[2][8][2];
#pragma unroll
        for (int s = 0; s < 2; s++) {
#pragma unroll
            for (int t = 0; t < 4; t++) {
                const uint32_t ap = Asb + (wm + t * 16 + gr) * GROW + s * 32 + gc * 4;
                af[s][t][0] = *(const uint32_t*)(smb + (ap - sb));
                af[s][t][1] = *(const uint32_t*)(smb + (ap - sb) + 8 * GROW);
                af[s][t][2] = *(const uint32_t*)(smb + (ap - sb) + 16);
                af[s][t][3] = *(const uint32_t*)(smb + (ap - sb) + 8 * GROW + 16);
            }
#pragma unroll
            for (int j = 0; j < 8; j++) {
                const uint32_t bp = Bsb + (wn + j * 8 + gr) * GROW + s * 32 + gc * 4;
                bf[s][j][0] = *(const uint32_t*)(smb + (bp - sb));
                bf[s][j][1] = *(const uint32_t*)(smb + (bp - sb) + 16);
            }
        }

        // pure MMA burst
#pragma unroll
        for (int s = 0; s < 2; s++)
#pragma unroll
            for (int t = 0; t < 4; t++)
#pragma unroll
                for (int j = 0; j < 8; j++)
                    mma_f16(acc[t][j], af[s][t], bf[s][j]);

        __syncthreads();

        const int kn = c + 2;
        if (kn < NK) {
            const uint32_t st = sb + stage * STG_BYTES;
#pragma unroll
            for (int u = 0; u < 2; u++) {
                CP_ASYNC16(st + ar * GROW + (au + u) * 16,
                           Ag + (size_t)kn * 32 + u * 8);
                CP_ASYNC16(st + (ar + 128) * GROW + (au + u) * 16,
                           Ag + (size_t)128 * K + kn * 32 + u * 8);
                CP_ASYNC16(st + STG_A + ar * GROW + (au + u) * 16,
                           Bg + (size_t)kn * 32 + u * 8);
            }
        }
        CP_COMMIT();
        stage ^= 1;
    }

    // epilogue
    const int col0 = bx * 128 + wn + 2 * gc;
    const int row0 = by * 256 + wm + gr;
    float2 bv[8];
#pragma unroll
    for (int j = 0; j < 8; j++)
        bv[j] = *(const float2*)(bias + col0 + j * 8);

#pragma unroll
    for (int t = 0; t < 4; t++) {
        const int r = row0 + t * 16;
#pragma unroll
        for (int j = 0; j < 8; j++) {
            float v0x = acc[t][j][0] + bv[j].x;
            float v0y = acc[t][j][1] + bv[j].y;
            float v1x = acc[t][j][2] + bv[j].x;
            float v1y = acc[t][j][3] + bv[j].y;
            if (OUTHALF) {
                __half* Cm = (__half*)Cv;
                *(__half2*)(Cm + (size_t)r * NOUT + col0 + j * 8) =
                    __floats2half2_rn(v0x, v0y);
                *(__half2*)(Cm + (size_t)(r + 8) * NOUT + col0 + j * 8) =
                    __floats2half2_rn(v1x, v1y);
            } else {
                float* Cm = (float*)Cv;
                float2 w0 = {v0x, v0y}, w1 = {v1x, v1y};
                *(float2*)(Cm + (size_t)r * NOUT + col0 + j * 8) = w0;
                *(float2*)(Cm + (size_t)(r + 8) * NOUT + col0 + j * 8) = w1;
            }
        }
    }
}

// ---------------------------------------------------------------------------
// fp16 tensor-core flash attention (causal). LPT scheduling: longest q-tiles
// (largest qt) mapped to the LOWEST block indices so they launch first.
// BQ=128, BK=64, HD=128, 256 threads (8 warps x 16 query rows).
// smem bytes: sQ[128][272] | sK[64][272] | sVt[128][144] | sP[128][144]
// ---------------------------------------------------------------------------
#define SQB 272
#define SKB 272
#define SVB 144
#define SPB 144
#define SQ_OFF  0
#define SK_OFF  (128 * SQB)                  // 34816
#define SVT_OFF (SK_OFF + 64 * SKB)          // 52224
#define SP_OFF  (SVT_OFF + 128 * SVB)        // 70656
#define FLASH_SMEM (SP_OFF + 128 * SPB)      // 89088

__global__ __launch_bounds__(256, 1) void flash_f16_kernel(
    const __half* __restrict__ qkv, __half* __restrict__ y)
{
    extern __shared__ uint8_t smb[];

    // LPT: reverse qt so long jobs (high qt) get low block ids -> launch first
    const int qt = (T_ / 128 - 1) - blockIdx.x;
    const int h = blockIdx.y, b = blockIdx.z;
    const int tid = threadIdx.x;
    const int lane = tid & 31, warp = tid >> 5;
    const int gr = lane >> 2, gc = lane & 3;
    const int m0 = warp * 16;
    const float scale = 0.08838834764831845f; // 1/sqrt(128)

    // ---- load Q tile ----
    {
        const int row = tid & 127;
        const int d0 = (tid >> 7) * 64;       // halves
        const uint4* qp = (const uint4*)(qkv
            + ((size_t)(b * T_ + qt * 128 + row)) * QKVN + h * HD + d0);
        uint8_t* dst = smb + SQ_OFF + row * SQB + d0 * 2;
#pragma unroll
        for (int it = 0; it < 8; it++)
            *(uint4*)(dst + it * 16) = qp[it];
    }

    float o[16][4];
#pragma unroll
    for (int j = 0; j < 16; j++)
#pragma unroll
        for (int c = 0; c < 4; c++) o[j][c] = 0.0f;
    float mrow[2] = {-1e30f, -1e30f};
    float lrow[2] = {0.0f, 0.0f};

    const int ktmax = 2 * qt + 1;
    for (int kt = 0; kt <= ktmax; kt++) {
        __syncthreads();

        // ---- load K (row-major) + V (transposed) ----
        {
            const int row = tid & 63;
            const int d0 = (tid >> 6) * 32;   // halves
            const __half* kp = qkv + ((size_t)(b * T_ + kt * 64 + row)) * QKVN
                               + C_ + h * HD + d0;
            const uint4* kpu = (const uint4*)kp;
            const uint4* vpu = (const uint4*)(kp + C_);
            uint8_t* kdst = smb + SK_OFF + row * SKB + d0 * 2;
#pragma unroll
            for (int it = 0; it < 4; it++)
                *(uint4*)(kdst + it * 16) = kpu[it];
#pragma unroll
            for (int it = 0; it < 4; it++) {
                uint4 v = vpu[it];
                uint32_t w[4] = {v.x, v.y, v.z, v.w};
                const int dbase = d0 + it * 8;
#pragma unroll
                for (int q = 0; q < 4; q++) {
                    uint8_t* p0 = smb + SVT_OFF + (dbase + 2 * q) * SVB + row * 2;
                    uint8_t* p1 = p0 + SVB;
                    *(uint16_t*)p0 = (uint16_t)(w[q] & 0xFFFFu);
                    *(uint16_t*)p1 = (uint16_t)(w[q] >> 16);
                }
            }
        }
        __syncthreads();

        if (qt * 128 + m0 + 15 < kt * 64) continue;

        // ---- S = Q @ K^T  (8 k16 steps, n64) ----
        float s[8][4];
#pragma unroll
        for (int j = 0; j < 8; j++)
#pragma unroll
            for (int c = 0; c < 4; c++) s[j][c] = 0.0f;

#pragma unroll
        for (int ks = 0; ks < 8; ks++) {
            uint32_t a[4];
            const uint8_t* ap = smb + SQ_OFF + (m0 + gr) * SQB + ks * 32 + gc * 4;
            a[0] = *(const uint32_t*)(ap);
            a[1] = *(const uint32_t*)(ap + 8 * SQB);
            a[2] = *(const uint32_t*)(ap + 16);
            a[3] = *(const uint32_t*)(ap + 8 * SQB + 16);
#pragma unroll
            for (int j = 0; j < 8; j++) {
                uint32_t bfr[2];
                const uint8_t* bp = smb + SK_OFF + (j * 8 + gr) * SKB + ks * 32 + gc * 4;
                bfr[0] = *(const uint32_t*)(bp);
                bfr[1] = *(const uint32_t*)(bp + 16);
                mma_f16(s[j], a, bfr);
            }
        }

        // ---- online softmax ----
#pragma unroll
        for (int r = 0; r < 2; r++) {
            const int qg = qt * 128 + m0 + gr + 8 * r;
            const bool need_mask = (kt * 64 + 63 > qg);
            float rm = -1e30f;
#pragma unroll
            for (int j = 0; j < 8; j++) {
#pragma unroll
                for (int c = 0; c < 2; c++) {
                    float v = s[j][2 * r + c] * scale;
                    if (need_mask && (kt * 64 + j * 8 + 2 * gc + c) > qg)
                        v = -1e30f;
                    s[j][2 * r + c] = v;
                    rm = fmaxf(rm, v);
                }
            }
            rm = fmaxf(rm, __shfl_xor_sync(0xffffffffu, rm, 1));
            rm = fmaxf(rm, __shfl_xor_sync(0xffffffffu, rm, 2));
            const float mnew = fmaxf(mrow[r], rm);
            const float corr = __expf(mrow[r] - mnew);
            float rsum = 0.0f;
#pragma unroll
            for (int j = 0; j < 8; j++) {
#pragma unroll
                for (int c = 0; c < 2; c++) {
                    float p = __expf(s[j][2 * r + c] - mnew);
                    s[j][2 * r + c] = p;
                    rsum += p;
                }
            }
            rsum += __shfl_xor_sync(0xffffffffu, rsum, 1);
            rsum += __shfl_xor_sync(0xffffffffu, rsum, 2);
            lrow[r] = lrow[r] * corr + rsum;
            mrow[r] = mnew;
#pragma unroll
            for (int j = 0; j < 16; j++) {
                o[j][2 * r + 0] *= corr;
                o[j][2 * r + 1] *= corr;
            }
        }

        // ---- stage P (fp16) ----
#pragma unroll
        for (int j = 0; j < 8; j++) {
            uint8_t* p0 = smb + SP_OFF + (m0 + gr) * SPB + j * 16 + gc * 4;
            *(uint32_t*)p0 = pack_h2(s[j][0], s[j][1]);
            *(uint32_t*)(p0 + 8 * SPB) = pack_h2(s[j][2], s[j][3]);
        }
        __syncwarp();

        // ---- O += P @ V  (4 k16 steps, n128) ----
#pragma unroll
        for (int ks = 0; ks < 4; ks++) {
            uint32_t a[4];
            const uint8_t* ap = smb + SP_OFF + (m0 + gr) * SPB + ks * 32 + gc * 4;
            a[0] = *(const uint32_t*)(ap);
            a[1] = *(const uint32_t*)(ap + 8 * SPB);
            a[2] = *(const uint32_t*)(ap + 16);
            a[3] = *(const uint32_t*)(ap + 8 * SPB + 16);
#pragma unroll
            for (int j = 0; j < 16; j++) {
                uint32_t bfr[2];
                const uint8_t* bp = smb + SVT_OFF + (j * 8 + gr) * SVB + ks * 32 + gc * 4;
                bfr[0] = *(const uint32_t*)(bp);
                bfr[1] = *(const uint32_t*)(bp + 16);
                mma_f16(o[j], a, bfr);
            }
        }
    }

    // ---- epilogue: O/l -> y (fp16) ----
    const float inv0 = 1.0f / lrow[0];
    const float inv1 = 1.0f / lrow[1];
#pragma unroll
    for (int r = 0; r < 2; r++) {
        const float inv = r ? inv1 : inv0;
        __half* yr = y + ((size_t)(b * T_ + qt * 128 + m0 + gr + 8 * r)) * C_
                     + h * HD + 2 * gc;
#pragma unroll
        for (int j = 0; j < 16; j++)
            *(__half2*)(yr + j * 8) =
                __floats2half2_rn(o[j][2 * r + 0] * inv, o[j][2 * r + 1] * inv);
    }
}

// ---------------------------------------------------------------------------
extern "C" void kernel_launch(void* const* d_in, const int* in_sizes, int n_in,
                              void* d_out, int out_size)
{
    const float* x      = (const float*)d_in[0];
    const float* W_attn = (const float*)d_in[1];
    const float* b_attn = (const float*)d_in[2];
    const float* W_proj = (const float*)d_in[3];
    const float* b_proj = (const float*)d_in[4];
    float* out = (float*)d_out;

    __half *qkv, *y, *xh, *wat, *wpt;
    cudaGetSymbolAddress((void**)&qkv, g_qkv);
    cudaGetSymbolAddress((void**)&y, g_y);
    cudaGetSymbolAddress((void**)&xh, g_xh);
    cudaGetSymbolAddress((void**)&wat, g_wat);
    cudaGetSymbolAddress((void**)&wpt, g_wpt);

    cudaFuncSetAttribute(gemm_f16_kernel<true>,
                         cudaFuncAttributeMaxDynamicSharedMemorySize, GEMM_SMEM);
    cudaFuncSetAttribute(gemm_f16_kernel<false>,
                         cudaFuncAttributeMaxDynamicSharedMemorySize, GEMM_SMEM);
    cudaFuncSetAttribute(flash_f16_kernel,
                         cudaFuncAttributeMaxDynamicSharedMemorySize, FLASH_SMEM);

    // 0) convert operands to fp16
    {
        int n4x = (ROWS * C_) / 4;
        f2h_kernel<<<(n4x + 255) / 256, 256>>>(
            (const float4*)x, (__half2*)xh, n4x);
        transpose_h_kernel<<<dim3(QKVN / 32, C_ / 32), dim3(32, 8)>>>(
            W_attn, wat, C_, QKVN);
        transpose_h_kernel<<<dim3(C_ / 32, C_ / 32), dim3(32, 8)>>>(
            W_proj, wpt, C_, C_);
    }

    // 1) QKV projection (fp16 out)
    gemm_f16_kernel<true><<<dim3(QKVN / 128, ROWS / 256), 256, GEMM_SMEM>>>(
        xh, wat, b_attn, qkv, C_, QKVN);
    // 2) Causal flash attention (LPT-ordered q-tiles)
    flash_f16_kernel<<<dim3(T_ / 128, NH, B_), 256, FLASH_SMEM>>>(qkv, y);
    // 3) Output projection (fp32 out)
    gemm_f16_kernel<false><<<dim3(C_ / 128, ROWS / 256), 256, GEMM_SMEM>>>(
        y, wpt, b_proj, out, C_, C_);
}